// round 8
// baseline (speedup 1.0000x reference)
#include <cuda_runtime.h>
#include <cuda.h>
#include <cuda_fp16.h>
#include <cstdint>
#include <cstddef>

#define TOKENS 8192
#define DIN    4096
#define DOUT   4096

// ---------------- scratch (allocation-free: device globals) ----------------
__device__ __align__(1024) __half g_A[(size_t)TOKENS * DIN];   // x in fp16, [M,K]
__device__ __align__(1024) __half g_B[(size_t)DOUT * DIN];     // W^T in fp16, [N,K]

// ---------------- helpers (defined before use) ----------------
__device__ __forceinline__ uint32_t h2_as_u32(__half2 h) {
    return *reinterpret_cast<uint32_t*>(&h);
}
__device__ __forceinline__ uint32_t smem_u32(const void* p) {
    uint32_t a;
    asm("{ .reg .u64 t; cvta.to.shared.u64 t, %1; cvt.u32.u64 %0, t; }" : "=r"(a) : "l"(p));
    return a;
}
__device__ __forceinline__ void mbar_init(uint32_t mbar, uint32_t cnt) {
    asm volatile("mbarrier.init.shared.b64 [%0], %1;" :: "r"(mbar), "r"(cnt) : "memory");
}
__device__ __forceinline__ void mbar_arrive(uint32_t mbar) {
    asm volatile("mbarrier.arrive.shared.b64 _, [%0];" :: "r"(mbar) : "memory");
}
__device__ __forceinline__ void mbar_arrive_expect(uint32_t mbar, uint32_t bytes) {
    asm volatile("mbarrier.arrive.expect_tx.shared.b64 _, [%0], %1;" :: "r"(mbar), "r"(bytes) : "memory");
}
__device__ __forceinline__ void mbar_wait(uint32_t mbar, uint32_t parity) {
    asm volatile(
        "{\n\t.reg .pred P;\n\t"
        "WL_%=:\n\t"
        "mbarrier.try_wait.parity.acquire.cta.shared::cta.b64 P, [%0], %1, 0x989680;\n\t"
        "@P bra.uni WD_%=;\n\t"
        "bra.uni WL_%=;\n\t"
        "WD_%=:\n\t}"
        :: "r"(mbar), "r"(parity) : "memory");
}
__device__ __forceinline__ void tma3d(uint32_t dst, const CUtensorMap* map,
                                      int cx, int cy, uint32_t mbar) {
    asm volatile(
        "cp.async.bulk.tensor.3d.shared::cta.global.tile.mbarrier::complete_tx::bytes "
        "[%0], [%1, {%2, %3, %4}], [%5];"
        :: "r"(dst), "l"(map), "r"(cx), "r"(cy), "r"(0), "r"(mbar) : "memory");
}
__device__ __forceinline__ void ldsm4(uint32_t* r, uint32_t addr) {
    asm volatile("ldmatrix.sync.aligned.m8n8.x4.shared.b16 {%0,%1,%2,%3}, [%4];"
                 : "=r"(r[0]), "=r"(r[1]), "=r"(r[2]), "=r"(r[3]) : "r"(addr));
}
// fp16-accumulate HMMA: D(f16x2 x2) = A*B + C, first step uses C=0
__device__ __forceinline__ void mma16816h_z(uint32_t* d, const uint32_t* a, const uint32_t* b) {
    asm volatile(
        "mma.sync.aligned.m16n8k16.row.col.f16.f16.f16.f16 "
        "{%0,%1}, {%2,%3,%4,%5}, {%6,%7}, {%8,%9};"
        : "=r"(d[0]), "=r"(d[1])
        : "r"(a[0]), "r"(a[1]), "r"(a[2]), "r"(a[3]), "r"(b[0]), "r"(b[1]),
          "r"(0u), "r"(0u));
}
__device__ __forceinline__ void mma16816h(uint32_t* d, const uint32_t* a, const uint32_t* b) {
    asm volatile(
        "mma.sync.aligned.m16n8k16.row.col.f16.f16.f16.f16 "
        "{%0,%1}, {%2,%3,%4,%5}, {%6,%7}, {%0,%1};"
        : "+r"(d[0]), "+r"(d[1])
        : "r"(a[0]), "r"(a[1]), "r"(a[2]), "r"(a[3]), "r"(b[0]), "r"(b[1]));
}

// ---------------- merged conversion kernel ----------------
static constexpr int XB = 2048;
static constexpr int WB = 2048;

__global__ void __launch_bounds__(256)
conv_all(const float4* __restrict__ x, const int* __restrict__ W) {
    const int tid = threadIdx.x;
    if (blockIdx.x < XB) {
        uint4* dst = reinterpret_cast<uint4*>(g_A);
        const size_t n4 = (size_t)TOKENS * DIN / 8;
        for (size_t i = (size_t)blockIdx.x * 256 + tid; i < n4; i += (size_t)XB * 256) {
            float4 v0 = x[2 * i];
            float4 v1 = x[2 * i + 1];
            uint4 o;
            o.x = h2_as_u32(__floats2half2_rn(v0.x, v0.y));
            o.y = h2_as_u32(__floats2half2_rn(v0.z, v0.w));
            o.z = h2_as_u32(__floats2half2_rn(v1.x, v1.y));
            o.w = h2_as_u32(__floats2half2_rn(v1.z, v1.w));
            dst[i] = o;
        }
    } else {
        __shared__ __half t[32][33];
        const int tx = tid & 31;
        const int ty = tid >> 5;
        const int wtiles = (DIN / 32) * (DOUT / 32);
        for (int tt = blockIdx.x - XB; tt < wtiles; tt += WB) {
            int tn = tt & 127, tk = tt >> 7;
            int n0 = tn * 32, k0 = tk * 32;
            __syncthreads();
#pragma unroll
            for (int j = 0; j < 32; j += 8)
                t[ty + j][tx] = __int2half_rn(W[(size_t)(k0 + ty + j) * DOUT + (n0 + tx)]);
            __syncthreads();
#pragma unroll
            for (int j = 0; j < 32; j += 8)
                g_B[(size_t)(n0 + ty + j) * DIN + (k0 + tx)] = t[tx][ty + j];
        }
    }
}

// ---------------- persistent GEMM: CTA 128x256x64, f16-accum chunks + f32 promote ----------------
static constexpr int NCTA = 148;
static constexpr int BM = 128, BN = 256, BK = 64;
static constexpr int S = 4;
static constexpr int KT = DIN / BK;                         // 64
static constexpr int NTILES = (TOKENS / BM) * (DOUT / BN);  // 1024
static constexpr uint32_t ABYTES = BM * BK * 2;
static constexpr uint32_t BBYTES = BN * BK * 2;
static constexpr uint32_t STAGE  = ABYTES + BBYTES;         // 49152
static constexpr uint32_t TXB    = STAGE;
static constexpr uint32_t SMEM_BYTES = S * STAGE + 1024 + 128;

__device__ __forceinline__ void tile_coords(int t, int& m0, int& n0) {
    int grp = t >> 7, r = t & 127;
    m0 = (grp * 8 + (r & 7)) * BM;
    n0 = (r >> 3) * BN;
}

__global__ void __launch_bounds__(256, 1)
gemm_persist(const __grid_constant__ CUtensorMap tmA,
             const __grid_constant__ CUtensorMap tmB,
             float* __restrict__ out) {
    extern __shared__ char smem[];
    const uint32_t sb    = smem_u32(smem);
    const uint32_t tiles = (sb + 1023u) & ~1023u;
    const uint32_t bar   = tiles + S * STAGE;
#define FULL(s)  (bar + (uint32_t)(s) * 16u)
#define EMPTY(s) (bar + (uint32_t)(s) * 16u + 8u)

    const int tid  = threadIdx.x;
    const int lane = tid & 31;
    const int wid  = tid >> 5;
    const int bid  = blockIdx.x;

    if (tid == 0) {
#pragma unroll
        for (int s = 0; s < S; s++) { mbar_init(FULL(s), 1); mbar_init(EMPTY(s), 8); }
    }
    __syncthreads();

    const int ntl   = (NTILES - bid + NCTA - 1) / NCTA;
    const int total = ntl * KT;

    const int wm = wid & 1, wn = wid >> 1;
    const int gq = lane >> 3;
    const uint32_t swz = (uint32_t)(lane & 7) << 4;
    uint32_t offA[4], offB[4];
#pragma unroll
    for (int i = 0; i < 4; i++) {
        int row = wm * 64 + i * 16 + (gq & 1) * 8 + (lane & 7);
        offA[i] = (uint32_t)row * 128u;
    }
#pragma unroll
    for (int j = 0; j < 4; j++) {
        int row = wn * 64 + j * 16 + (gq >> 1) * 8 + (lane & 7);
        offB[j] = ABYTES + (uint32_t)row * 128u;
    }
    const uint32_t selA = (uint32_t)(gq >> 1) * 16u;
    const uint32_t selB = (uint32_t)(gq & 1) * 16u;

    float acc[4][8][4];
#pragma unroll
    for (int i = 0; i < 4; i++)
#pragma unroll
        for (int j = 0; j < 8; j++)
#pragma unroll
            for (int v = 0; v < 4; v++) acc[i][j][v] = 0.f;

    auto fillq = [&](int q) {
        int t = bid + (q >> 6) * NCTA;
        int m0, n0; tile_coords(t, m0, n0);
        int kb = q & (KT - 1);
        int s  = q & (S - 1);
        uint32_t base = tiles + (uint32_t)s * STAGE;
        mbar_arrive_expect(FULL(s), TXB);
        tma3d(base,          &tmA, kb * BK, m0, FULL(s));
        tma3d(base + ABYTES, &tmB, kb * BK, n0, FULL(s));
    };

    if (tid == 0) {
#pragma unroll
        for (int q = 0; q < S - 1; q++) if (q < total) fillq(q);
    }

#pragma unroll 1
    for (int i = 0; i < total; i++) {
        const int s = i & (S - 1);

        if (tid == 0) {
            const int q = i + S - 1;
            if (q < total) {
                if (q >= S) mbar_wait(EMPTY(q & (S - 1)), ((uint32_t)(q >> 2) + 1u) & 1u);
                fillq(q);
            }
        }

        mbar_wait(FULL(s), (uint32_t)(i >> 2) & 1u);
        const uint32_t base = tiles + (uint32_t)s * STAGE;

        // f16-accumulate over this BK=64 chunk (4 k16 steps), then promote to f32
        uint32_t hacc[4][8][2];
#pragma unroll
        for (int ks = 0; ks < 4; ks++) {
            const uint32_t ckA = (((uint32_t)ks * 2u) * 16u + selA) ^ swz;
            const uint32_t ckB = (((uint32_t)ks * 2u) * 16u + selB) ^ swz;
            uint32_t a[4][4], b[4][4];
#pragma unroll
            for (int ii = 0; ii < 4; ii++) ldsm4(a[ii], base + offA[ii] + ckA);
#pragma unroll
            for (int jj = 0; jj < 4; jj++) ldsm4(b[jj], base + offB[jj] + ckB);
#pragma unroll
            for (int ii = 0; ii < 4; ii++)
#pragma unroll
                for (int jj = 0; jj < 4; jj++) {
                    if (ks == 0) {
                        mma16816h_z(hacc[ii][2 * jj],     a[ii], &b[jj][0]);
                        mma16816h_z(hacc[ii][2 * jj + 1], a[ii], &b[jj][2]);
                    } else {
                        mma16816h(hacc[ii][2 * jj],     a[ii], &b[jj][0]);
                        mma16816h(hacc[ii][2 * jj + 1], a[ii], &b[jj][2]);
                    }
                }
        }
        if (lane == 0) mbar_arrive(EMPTY(s));

        // promote chunk sums into f32 accumulators (fma/alu pipe, overlaps next chunk's TMA)
#pragma unroll
        for (int ii = 0; ii < 4; ii++)
#pragma unroll
            for (int jn = 0; jn < 8; jn++) {
                float2 lo = __half22float2(*reinterpret_cast<__half2*>(&hacc[ii][jn][0]));
                float2 hi = __half22float2(*reinterpret_cast<__half2*>(&hacc[ii][jn][1]));
                acc[ii][jn][0] += lo.x;
                acc[ii][jn][1] += lo.y;
                acc[ii][jn][2] += hi.x;
                acc[ii][jn][3] += hi.y;
            }

        // tile done -> epilogue (overlaps next tile's TMA prefetch)
        if ((i & (KT - 1)) == KT - 1) {
            int t = bid + (i >> 6) * NCTA;
            int m0, n0; tile_coords(t, m0, n0);
            const int mrow = m0 + wm * 64 + (lane >> 2);
            const int ncol = n0 + wn * 64 + (lane & 3) * 2;
#pragma unroll
            for (int ii = 0; ii < 4; ii++) {
#pragma unroll
                for (int jn = 0; jn < 8; jn++) {
                    float2 v0 = make_float2(acc[ii][jn][0], acc[ii][jn][1]);
                    float2 v1 = make_float2(acc[ii][jn][2], acc[ii][jn][3]);
                    *reinterpret_cast<float2*>(out + (size_t)(mrow + ii * 16) * DOUT + ncol + jn * 8)     = v0;
                    *reinterpret_cast<float2*>(out + (size_t)(mrow + ii * 16 + 8) * DOUT + ncol + jn * 8) = v1;
#pragma unroll
                    for (int v = 0; v < 4; v++) acc[ii][jn][v] = 0.f;
                }
            }
        }
    }
#undef FULL
#undef EMPTY
}

// ---------------- host launch ----------------
typedef CUresult (*encode_fn_t)(CUtensorMap*, CUtensorMapDataType, cuuint32_t, void*,
                                const cuuint64_t*, const cuuint64_t*, const cuuint32_t*,
                                const cuuint32_t*, CUtensorMapInterleave, CUtensorMapSwizzle,
                                CUtensorMapL2promotion, CUtensorMapFloatOOBfill);

extern "C" void kernel_launch(void* const* d_in, const int* in_sizes, int n_in,
                              void* d_out, int out_size) {
    const float* x = (const float*)d_in[0];
    const int*   W = (const int*)d_in[1];
    float* out = (float*)d_out;

    void* pa = nullptr; void* pb = nullptr;
    cudaGetSymbolAddress(&pa, g_A);
    cudaGetSymbolAddress(&pb, g_B);

    static encode_fn_t enc = nullptr;
    if (!enc) {
        cudaDriverEntryPointQueryResult st;
        cudaGetDriverEntryPointByVersion("cuTensorMapEncodeTiled", (void**)&enc,
                                         12000, cudaEnableDefault, &st);
    }
    CUtensorMap mA{}, mB{};
    {
        cuuint64_t dims[3] = {DIN, TOKENS, 1};
        cuuint64_t str[2]  = {DIN * 2ull, (cuuint64_t)TOKENS * DIN * 2ull};
        cuuint32_t box[3]  = {64, 128, 1};
        cuuint32_t es[3]   = {1, 1, 1};
        enc(&mA, CU_TENSOR_MAP_DATA_TYPE_FLOAT16, 3, pa, dims, str, box, es,
            CU_TENSOR_MAP_INTERLEAVE_NONE, CU_TENSOR_MAP_SWIZZLE_128B,
            CU_TENSOR_MAP_L2_PROMOTION_L2_128B, CU_TENSOR_MAP_FLOAT_OOB_FILL_NONE);
    }
    {
        cuuint64_t dims[3] = {DIN, DOUT, 1};
        cuuint64_t str[2]  = {DIN * 2ull, (cuuint64_t)DOUT * DIN * 2ull};
        cuuint32_t box[3]  = {64, 256, 1};
        cuuint32_t es[3]   = {1, 1, 1};
        enc(&mB, CU_TENSOR_MAP_DATA_TYPE_FLOAT16, 3, pb, dims, str, box, es,
            CU_TENSOR_MAP_INTERLEAVE_NONE, CU_TENSOR_MAP_SWIZZLE_128B,
            CU_TENSOR_MAP_L2_PROMOTION_L2_128B, CU_TENSOR_MAP_FLOAT_OOB_FILL_NONE);
    }

    conv_all<<<XB + WB, 256>>>((const float4*)x, W);

    cudaFuncSetAttribute(gemm_persist, cudaFuncAttributeMaxDynamicSharedMemorySize, SMEM_BYTES);
    gemm_persist<<<NCTA, 256, SMEM_BYTES>>>(mA, mB, out);
}

// round 9
// speedup vs baseline: 1.2831x; 1.2831x over previous
#include <cuda_runtime.h>
#include <cuda.h>
#include <cuda_fp16.h>
#include <cstdint>
#include <cstddef>

#define TOKENS 8192
#define DIN    4096
#define DOUT   4096

// ---------------- scratch (allocation-free: device globals) ----------------
__device__ __align__(1024) __half g_A[(size_t)TOKENS * DIN];   // x in fp16, [M,K]
__device__ __align__(1024) __half g_B[(size_t)DOUT * DIN];     // W^T in fp16, [N,K]

// ---------------- helpers (defined before use) ----------------
__device__ __forceinline__ uint32_t h2_as_u32(__half2 h) {
    return *reinterpret_cast<uint32_t*>(&h);
}
__device__ __forceinline__ uint32_t smem_u32(const void* p) {
    uint32_t a;
    asm("{ .reg .u64 t; cvta.to.shared.u64 t, %1; cvt.u32.u64 %0, t; }" : "=r"(a) : "l"(p));
    return a;
}
__device__ __forceinline__ void mbar_init(uint32_t mbar, uint32_t cnt) {
    asm volatile("mbarrier.init.shared.b64 [%0], %1;" :: "r"(mbar), "r"(cnt) : "memory");
}
__device__ __forceinline__ void mbar_arrive(uint32_t mbar) {
    asm volatile("mbarrier.arrive.shared.b64 _, [%0];" :: "r"(mbar) : "memory");
}
__device__ __forceinline__ void mbar_arrive_expect(uint32_t mbar, uint32_t bytes) {
    asm volatile("mbarrier.arrive.expect_tx.shared.b64 _, [%0], %1;" :: "r"(mbar), "r"(bytes) : "memory");
}
__device__ __forceinline__ void mbar_wait(uint32_t mbar, uint32_t parity) {
    asm volatile(
        "{\n\t.reg .pred P;\n\t"
        "WL_%=:\n\t"
        "mbarrier.try_wait.parity.acquire.cta.shared::cta.b64 P, [%0], %1, 0x989680;\n\t"
        "@P bra.uni WD_%=;\n\t"
        "bra.uni WL_%=;\n\t"
        "WD_%=:\n\t}"
        :: "r"(mbar), "r"(parity) : "memory");
}
__device__ __forceinline__ void tma3d(uint32_t dst, const CUtensorMap* map,
                                      int cx, int cy, uint32_t mbar) {
    asm volatile(
        "cp.async.bulk.tensor.3d.shared::cta.global.tile.mbarrier::complete_tx::bytes "
        "[%0], [%1, {%2, %3, %4}], [%5];"
        :: "r"(dst), "l"(map), "r"(cx), "r"(cy), "r"(0), "r"(mbar) : "memory");
}
__device__ __forceinline__ void ldsm4(uint32_t* r, uint32_t addr) {
    asm volatile("ldmatrix.sync.aligned.m8n8.x4.shared.b16 {%0,%1,%2,%3}, [%4];"
                 : "=r"(r[0]), "=r"(r[1]), "=r"(r[2]), "=r"(r[3]) : "r"(addr));
}
__device__ __forceinline__ void mma16816(float* d, const uint32_t* a, const uint32_t* b) {
    asm volatile(
        "mma.sync.aligned.m16n8k16.row.col.f32.f16.f16.f32 "
        "{%0,%1,%2,%3}, {%4,%5,%6,%7}, {%8,%9}, {%0,%1,%2,%3};"
        : "+f"(d[0]), "+f"(d[1]), "+f"(d[2]), "+f"(d[3])
        : "r"(a[0]), "r"(a[1]), "r"(a[2]), "r"(a[3]), "r"(b[0]), "r"(b[1]));
}

// ---------------- merged conversion kernel (proven) ----------------
static constexpr int XB = 2048;
static constexpr int WB = 2048;

__global__ void __launch_bounds__(256)
conv_all(const float4* __restrict__ x, const int* __restrict__ W) {
    const int tid = threadIdx.x;
    if (blockIdx.x < XB) {
        uint4* dst = reinterpret_cast<uint4*>(g_A);
        const size_t n4 = (size_t)TOKENS * DIN / 8;
        for (size_t i = (size_t)blockIdx.x * 256 + tid; i < n4; i += (size_t)XB * 256) {
            float4 v0 = x[2 * i];
            float4 v1 = x[2 * i + 1];
            uint4 o;
            o.x = h2_as_u32(__floats2half2_rn(v0.x, v0.y));
            o.y = h2_as_u32(__floats2half2_rn(v0.z, v0.w));
            o.z = h2_as_u32(__floats2half2_rn(v1.x, v1.y));
            o.w = h2_as_u32(__floats2half2_rn(v1.z, v1.w));
            dst[i] = o;
        }
    } else {
        __shared__ __half t[32][33];
        const int tx = tid & 31;
        const int ty = tid >> 5;
        const int wtiles = (DIN / 32) * (DOUT / 32);
        for (int tt = blockIdx.x - XB; tt < wtiles; tt += WB) {
            int tn = tt & 127, tk = tt >> 7;
            int n0 = tn * 32, k0 = tk * 32;
            __syncthreads();
#pragma unroll
            for (int j = 0; j < 32; j += 8)
                t[ty + j][tx] = __int2half_rn(W[(size_t)(k0 + ty + j) * DOUT + (n0 + tx)]);
            __syncthreads();
#pragma unroll
            for (int j = 0; j < 32; j += 8)
                g_B[(size_t)(n0 + ty + j) * DIN + (k0 + tx)] = t[tx][ty + j];
        }
    }
}

// ---------------- persistent GEMM: CTA 128x256x128, S=2, f32-accum HMMA ----------------
static constexpr int NCTA = 148;
static constexpr int BM = 128, BN = 256, BK = 128;
static constexpr int S = 2;
static constexpr int KT = DIN / BK;                         // 32 k-blocks per tile
static constexpr int NTILES = (TOKENS / BM) * (DOUT / BN);  // 1024
static constexpr uint32_t APANEL = BM * 64 * 2;             // 16384 (64-wide SW128 panel)
static constexpr uint32_t BPANEL = BN * 64 * 2;             // 32768
static constexpr uint32_t AREG   = 2 * APANEL;              // 32768
static constexpr uint32_t STAGE  = AREG + 2 * BPANEL;       // 98304
static constexpr uint32_t TXB    = STAGE;
static constexpr uint32_t SMEM_BYTES = S * STAGE + 1024 + 128;  // ~197.8 KB

__device__ __forceinline__ void tile_coords(int t, int& m0, int& n0) {
    int grp = t >> 7, r = t & 127;
    m0 = (grp * 8 + (r & 7)) * BM;   // 8 m-tiles per group (L2-friendly raster)
    n0 = (r >> 3) * BN;
}

__global__ void __launch_bounds__(256, 1)
gemm_persist(const __grid_constant__ CUtensorMap tmA,
             const __grid_constant__ CUtensorMap tmB,
             float* __restrict__ out) {
    extern __shared__ char smem[];
    const uint32_t sb    = smem_u32(smem);
    const uint32_t tiles = (sb + 1023u) & ~1023u;
    const uint32_t bar   = tiles + S * STAGE;
#define FULL(s)  (bar + (uint32_t)(s) * 16u)
#define EMPTY(s) (bar + (uint32_t)(s) * 16u + 8u)

    const int tid  = threadIdx.x;
    const int lane = tid & 31;
    const int wid  = tid >> 5;
    const int bid  = blockIdx.x;

    if (tid == 0) {
#pragma unroll
        for (int s = 0; s < S; s++) { mbar_init(FULL(s), 1); mbar_init(EMPTY(s), 8); }
    }
    __syncthreads();

    const int ntl   = (NTILES - bid + NCTA - 1) / NCTA;
    const int total = ntl * KT;

    // ldmatrix swizzled offsets within a 64-wide panel
    const int wm = wid & 1, wn = wid >> 1;
    const int gq = lane >> 3;
    const uint32_t swz = (uint32_t)(lane & 7) << 4;
    uint32_t offA[4], offB[4];
#pragma unroll
    for (int i = 0; i < 4; i++) {
        int row = wm * 64 + i * 16 + (gq & 1) * 8 + (lane & 7);
        offA[i] = (uint32_t)row * 128u;
    }
#pragma unroll
    for (int j = 0; j < 4; j++) {
        int row = wn * 64 + j * 16 + (gq >> 1) * 8 + (lane & 7);
        offB[j] = (uint32_t)row * 128u;
    }
    const uint32_t selA = (uint32_t)(gq >> 1) * 16u;
    const uint32_t selB = (uint32_t)(gq & 1) * 16u;

    float acc[4][8][4];
#pragma unroll
    for (int i = 0; i < 4; i++)
#pragma unroll
        for (int j = 0; j < 8; j++)
#pragma unroll
            for (int v = 0; v < 4; v++) acc[i][j][v] = 0.f;

    // producer fill of flat index q (enumerates (tile, kb) pairs)
    auto fillq = [&](int q) {
        int t = bid + (q >> 5) * NCTA;
        int m0, n0; tile_coords(t, m0, n0);
        int kx = (q & (KT - 1)) * BK;
        int s  = q & (S - 1);
        uint32_t base = tiles + (uint32_t)s * STAGE;
        mbar_arrive_expect(FULL(s), TXB);
        tma3d(base,                   &tmA, kx,      m0, FULL(s));
        tma3d(base + APANEL,          &tmA, kx + 64, m0, FULL(s));
        tma3d(base + AREG,            &tmB, kx,      n0, FULL(s));
        tma3d(base + AREG + BPANEL,   &tmB, kx + 64, n0, FULL(s));
    };

    if (tid == 0) {
        if (0 < total) fillq(0);   // prologue: S-1 = 1 stage
    }

#pragma unroll 1
    for (int i = 0; i < total; i++) {
        const int s = i & (S - 1);

        // producer keeps pipeline full across tile boundaries
        if (tid == 0) {
            const int q = i + S - 1;
            if (q < total) {
                if (q >= S) mbar_wait(EMPTY(q & (S - 1)), ((uint32_t)(q >> 1) + 1u) & 1u);
                fillq(q);
            }
        }

        mbar_wait(FULL(s), (uint32_t)(i >> 1) & 1u);
        const uint32_t base = tiles + (uint32_t)s * STAGE;

#pragma unroll
        for (int ks = 0; ks < 8; ks++) {
            const uint32_t pa = base + (uint32_t)(ks >> 2) * APANEL;
            const uint32_t pb = base + AREG + (uint32_t)(ks >> 2) * BPANEL;
            const uint32_t ckA = (((uint32_t)(ks & 3) * 32u) + selA) ^ swz;
            const uint32_t ckB = (((uint32_t)(ks & 3) * 32u) + selB) ^ swz;
            uint32_t a[4][4], b[4][4];
#pragma unroll
            for (int ii = 0; ii < 4; ii++) ldsm4(a[ii], pa + offA[ii] + ckA);
#pragma unroll
            for (int jj = 0; jj < 4; jj++) ldsm4(b[jj], pb + offB[jj] + ckB);
#pragma unroll
            for (int ii = 0; ii < 4; ii++)
#pragma unroll
                for (int jj = 0; jj < 4; jj++) {
                    mma16816(acc[ii][2 * jj],     a[ii], &b[jj][0]);
                    mma16816(acc[ii][2 * jj + 1], a[ii], &b[jj][2]);
                }
        }
        if (lane == 0) mbar_arrive(EMPTY(s));

        // tile done -> epilogue (overlaps next tile's TMA prefetch)
        if ((i & (KT - 1)) == KT - 1) {
            int t = bid + (i >> 5) * NCTA;
            int m0, n0; tile_coords(t, m0, n0);
            const int mrow = m0 + wm * 64 + (lane >> 2);
            const int ncol = n0 + wn * 64 + (lane & 3) * 2;
#pragma unroll
            for (int ii = 0; ii < 4; ii++) {
#pragma unroll
                for (int jn = 0; jn < 8; jn++) {
                    float2 v0 = make_float2(acc[ii][jn][0], acc[ii][jn][1]);
                    float2 v1 = make_float2(acc[ii][jn][2], acc[ii][jn][3]);
                    *reinterpret_cast<float2*>(out + (size_t)(mrow + ii * 16) * DOUT + ncol + jn * 8)     = v0;
                    *reinterpret_cast<float2*>(out + (size_t)(mrow + ii * 16 + 8) * DOUT + ncol + jn * 8) = v1;
#pragma unroll
                    for (int v = 0; v < 4; v++) acc[ii][jn][v] = 0.f;
                }
            }
        }
    }
#undef FULL
#undef EMPTY
}

// ---------------- host launch ----------------
typedef CUresult (*encode_fn_t)(CUtensorMap*, CUtensorMapDataType, cuuint32_t, void*,
                                const cuuint64_t*, const cuuint64_t*, const cuuint32_t*,
                                const cuuint32_t*, CUtensorMapInterleave, CUtensorMapSwizzle,
                                CUtensorMapL2promotion, CUtensorMapFloatOOBfill);

extern "C" void kernel_launch(void* const* d_in, const int* in_sizes, int n_in,
                              void* d_out, int out_size) {
    const float* x = (const float*)d_in[0];
    const int*   W = (const int*)d_in[1];
    float* out = (float*)d_out;

    void* pa = nullptr; void* pb = nullptr;
    cudaGetSymbolAddress(&pa, g_A);
    cudaGetSymbolAddress(&pb, g_B);

    static encode_fn_t enc = nullptr;
    if (!enc) {
        cudaDriverEntryPointQueryResult st;
        cudaGetDriverEntryPointByVersion("cuTensorMapEncodeTiled", (void**)&enc,
                                         12000, cudaEnableDefault, &st);
    }
    CUtensorMap mA{}, mB{};
    {
        cuuint64_t dims[3] = {DIN, TOKENS, 1};
        cuuint64_t str[2]  = {DIN * 2ull, (cuuint64_t)TOKENS * DIN * 2ull};
        cuuint32_t box[3]  = {64, 128, 1};
        cuuint32_t es[3]   = {1, 1, 1};
        enc(&mA, CU_TENSOR_MAP_DATA_TYPE_FLOAT16, 3, pa, dims, str, box, es,
            CU_TENSOR_MAP_INTERLEAVE_NONE, CU_TENSOR_MAP_SWIZZLE_128B,
            CU_TENSOR_MAP_L2_PROMOTION_L2_128B, CU_TENSOR_MAP_FLOAT_OOB_FILL_NONE);
    }
    {
        cuuint64_t dims[3] = {DIN, DOUT, 1};
        cuuint64_t str[2]  = {DIN * 2ull, (cuuint64_t)DOUT * DIN * 2ull};
        cuuint32_t box[3]  = {64, 256, 1};
        cuuint32_t es[3]   = {1, 1, 1};
        enc(&mB, CU_TENSOR_MAP_DATA_TYPE_FLOAT16, 3, pb, dims, str, box, es,
            CU_TENSOR_MAP_INTERLEAVE_NONE, CU_TENSOR_MAP_SWIZZLE_128B,
            CU_TENSOR_MAP_L2_PROMOTION_L2_128B, CU_TENSOR_MAP_FLOAT_OOB_FILL_NONE);
    }

    conv_all<<<XB + WB, 256>>>((const float4*)x, W);

    cudaFuncSetAttribute(gemm_persist, cudaFuncAttributeMaxDynamicSharedMemorySize, SMEM_BYTES);
    gemm_persist<<<NCTA, 256, SMEM_BYTES>>>(mA, mB, out);
}

// round 10
// speedup vs baseline: 1.3025x; 1.0152x over previous
#include <cuda_runtime.h>
#include <cuda.h>
#include <cuda_fp16.h>
#include <cstdint>
#include <cstddef>

#define TOKENS 8192
#define DIN    4096
#define DOUT   4096

// ---------------- scratch (allocation-free: device globals) ----------------
__device__ __align__(1024) __half g_A[(size_t)TOKENS * DIN];   // x in fp16, [M,K]
__device__ __align__(1024) __half g_B[(size_t)DOUT * DIN];     // W^T in fp16, [N,K]

// ---------------- helpers (defined before use) ----------------
__device__ __forceinline__ uint32_t h2_as_u32(__half2 h) {
    return *reinterpret_cast<uint32_t*>(&h);
}
__device__ __forceinline__ uint32_t smem_u32(const void* p) {
    uint32_t a;
    asm("{ .reg .u64 t; cvta.to.shared.u64 t, %1; cvt.u32.u64 %0, t; }" : "=r"(a) : "l"(p));
    return a;
}
__device__ __forceinline__ void mbar_init(uint32_t mbar, uint32_t cnt) {
    asm volatile("mbarrier.init.shared.b64 [%0], %1;" :: "r"(mbar), "r"(cnt) : "memory");
}
__device__ __forceinline__ void mbar_arrive(uint32_t mbar) {
    asm volatile("mbarrier.arrive.shared.b64 _, [%0];" :: "r"(mbar) : "memory");
}
__device__ __forceinline__ void mbar_arrive_expect(uint32_t mbar, uint32_t bytes) {
    asm volatile("mbarrier.arrive.expect_tx.shared.b64 _, [%0], %1;" :: "r"(mbar), "r"(bytes) : "memory");
}
__device__ __forceinline__ void mbar_wait(uint32_t mbar, uint32_t parity) {
    asm volatile(
        "{\n\t.reg .pred P;\n\t"
        "WL_%=:\n\t"
        "mbarrier.try_wait.parity.acquire.cta.shared::cta.b64 P, [%0], %1, 0x989680;\n\t"
        "@P bra.uni WD_%=;\n\t"
        "bra.uni WL_%=;\n\t"
        "WD_%=:\n\t}"
        :: "r"(mbar), "r"(parity) : "memory");
}
__device__ __forceinline__ void tma3d(uint32_t dst, const CUtensorMap* map,
                                      int cx, int cy, uint32_t mbar) {
    asm volatile(
        "cp.async.bulk.tensor.3d.shared::cta.global.tile.mbarrier::complete_tx::bytes "
        "[%0], [%1, {%2, %3, %4}], [%5];"
        :: "r"(dst), "l"(map), "r"(cx), "r"(cy), "r"(0), "r"(mbar) : "memory");
}
__device__ __forceinline__ void ldsm4(uint32_t* r, uint32_t addr) {
    asm volatile("ldmatrix.sync.aligned.m8n8.x4.shared.b16 {%0,%1,%2,%3}, [%4];"
                 : "=r"(r[0]), "=r"(r[1]), "=r"(r[2]), "=r"(r[3]) : "r"(addr));
}
__device__ __forceinline__ void mma16816(float* d, const uint32_t* a, const uint32_t* b) {
    asm volatile(
        "mma.sync.aligned.m16n8k16.row.col.f32.f16.f16.f32 "
        "{%0,%1,%2,%3}, {%4,%5,%6,%7}, {%8,%9}, {%0,%1,%2,%3};"
        : "+f"(d[0]), "+f"(d[1]), "+f"(d[2]), "+f"(d[3])
        : "r"(a[0]), "r"(a[1]), "r"(a[2]), "r"(a[3]), "r"(b[0]), "r"(b[1]));
}

// ---------------- merged conversion kernel ----------------
static constexpr int XB = 2048;
static constexpr int WB = 2048;

__global__ void __launch_bounds__(256)
conv_all(const float4* __restrict__ x, const int* __restrict__ W) {
    const int tid = threadIdx.x;
    if (blockIdx.x < XB) {
        uint4* dst = reinterpret_cast<uint4*>(g_A);
        const size_t n4 = (size_t)TOKENS * DIN / 8;   // 4,194,304 uint4s
        const size_t stride = (size_t)XB * 256;
        size_t i = (size_t)blockIdx.x * 256 + tid;
        // 8 iterations/thread; unroll 2 for deeper MLP
#pragma unroll 2
        for (; i < n4; i += stride) {
            float4 v0 = x[2 * i];
            float4 v1 = x[2 * i + 1];
            uint4 o;
            o.x = h2_as_u32(__floats2half2_rn(v0.x, v0.y));
            o.y = h2_as_u32(__floats2half2_rn(v0.z, v0.w));
            o.z = h2_as_u32(__floats2half2_rn(v1.x, v1.y));
            o.w = h2_as_u32(__floats2half2_rn(v1.z, v1.w));
            dst[i] = o;
        }
    } else {
        __shared__ __half t[32][33];
        const int tx = tid & 31;
        const int ty = tid >> 5;
        const int wtiles = (DIN / 32) * (DOUT / 32);
        for (int tt = blockIdx.x - XB; tt < wtiles; tt += WB) {
            int tn = tt & 127, tk = tt >> 7;
            int n0 = tn * 32, k0 = tk * 32;
            __syncthreads();
#pragma unroll
            for (int j = 0; j < 32; j += 8)
                t[ty + j][tx] = __int2half_rn(W[(size_t)(k0 + ty + j) * DOUT + (n0 + tx)]);
            __syncthreads();
#pragma unroll
            for (int j = 0; j < 32; j += 8)
                g_B[(size_t)(n0 + ty + j) * DIN + (k0 + tx)] = t[tx][ty + j];
        }
    }
}

// ---------------- persistent GEMM: CTA 128x256x64, S=4, frag double-buffer ----------------
static constexpr int NCTA = 148;
static constexpr int BM = 128, BN = 256, BK = 64;
static constexpr int S = 4;
static constexpr int KT = DIN / BK;                         // 64
static constexpr int NTILES = (TOKENS / BM) * (DOUT / BN);  // 1024
static constexpr uint32_t ABYTES = BM * BK * 2;             // 16384
static constexpr uint32_t BBYTES = BN * BK * 2;             // 32768
static constexpr uint32_t STAGE  = ABYTES + BBYTES;         // 49152
static constexpr uint32_t TXB    = STAGE;
static constexpr uint32_t SMEM_BYTES = S * STAGE + 1024 + 128;

__device__ __forceinline__ void tile_coords(int t, int& m0, int& n0) {
    int grp = t >> 7, r = t & 127;
    m0 = (grp * 8 + (r & 7)) * BM;
    n0 = (r >> 3) * BN;
}

__global__ void __launch_bounds__(256, 1)
gemm_persist(const __grid_constant__ CUtensorMap tmA,
             const __grid_constant__ CUtensorMap tmB,
             float* __restrict__ out) {
    extern __shared__ char smem[];
    const uint32_t sb    = smem_u32(smem);
    const uint32_t tiles = (sb + 1023u) & ~1023u;
    const uint32_t bar   = tiles + S * STAGE;
#define FULL(s)  (bar + (uint32_t)(s) * 16u)
#define EMPTY(s) (bar + (uint32_t)(s) * 16u + 8u)

    const int tid  = threadIdx.x;
    const int lane = tid & 31;
    const int wid  = tid >> 5;
    const int bid  = blockIdx.x;

    if (tid == 0) {
#pragma unroll
        for (int s = 0; s < S; s++) { mbar_init(FULL(s), 1); mbar_init(EMPTY(s), 8); }
    }
    __syncthreads();

    const int ntl   = (NTILES - bid + NCTA - 1) / NCTA;
    const int total = ntl * KT;

    const int wm = wid & 1, wn = wid >> 1;
    const int gq = lane >> 3;
    const uint32_t swz = (uint32_t)(lane & 7) << 4;
    uint32_t offA[4], offB[4];
#pragma unroll
    for (int i = 0; i < 4; i++) {
        int row = wm * 64 + i * 16 + (gq & 1) * 8 + (lane & 7);
        offA[i] = (uint32_t)row * 128u;
    }
#pragma unroll
    for (int j = 0; j < 4; j++) {
        int row = wn * 64 + j * 16 + (gq >> 1) * 8 + (lane & 7);
        offB[j] = ABYTES + (uint32_t)row * 128u;
    }
    const uint32_t selA = (uint32_t)(gq >> 1) * 16u;
    const uint32_t selB = (uint32_t)(gq & 1) * 16u;

    float acc[4][8][4];
#pragma unroll
    for (int i = 0; i < 4; i++)
#pragma unroll
        for (int j = 0; j < 8; j++)
#pragma unroll
            for (int v = 0; v < 4; v++) acc[i][j][v] = 0.f;

    auto fillq = [&](int q) {
        int t = bid + (q >> 6) * NCTA;
        int m0, n0; tile_coords(t, m0, n0);
        int kb = q & (KT - 1);
        int s  = q & (S - 1);
        uint32_t base = tiles + (uint32_t)s * STAGE;
        mbar_arrive_expect(FULL(s), TXB);
        tma3d(base,          &tmA, kb * BK, m0, FULL(s));
        tma3d(base + ABYTES, &tmB, kb * BK, n0, FULL(s));
    };

    if (tid == 0) {
#pragma unroll
        for (int q = 0; q < S - 1; q++) if (q < total) fillq(q);
    }

#pragma unroll 1
    for (int i = 0; i < total; i++) {
        const int s = i & (S - 1);

        if (tid == 0) {
            const int q = i + S - 1;
            if (q < total) {
                if (q >= S) mbar_wait(EMPTY(q & (S - 1)), ((uint32_t)(q >> 2) + 1u) & 1u);
                fillq(q);
            }
        }

        mbar_wait(FULL(s), (uint32_t)(i >> 2) & 1u);
        const uint32_t base = tiles + (uint32_t)s * STAGE;

        // fragment double-buffer: issue ldsm for ks+1 before mma block of ks
        uint32_t a[2][4][4], b[2][4][4];
        {
            const uint32_t ckA0 = selA ^ swz;
            const uint32_t ckB0 = selB ^ swz;
#pragma unroll
            for (int ii = 0; ii < 4; ii++) ldsm4(a[0][ii], base + offA[ii] + ckA0);
#pragma unroll
            for (int jj = 0; jj < 4; jj++) ldsm4(b[0][jj], base + offB[jj] + ckB0);
        }
#pragma unroll
        for (int ks = 0; ks < 4; ks++) {
            const int cur = ks & 1;
            const int nxt = cur ^ 1;
            if (ks < 3) {
                const uint32_t ckA = (((uint32_t)(ks + 1) * 32u) + selA) ^ swz;
                const uint32_t ckB = (((uint32_t)(ks + 1) * 32u) + selB) ^ swz;
#pragma unroll
                for (int ii = 0; ii < 4; ii++) ldsm4(a[nxt][ii], base + offA[ii] + ckA);
#pragma unroll
                for (int jj = 0; jj < 4; jj++) ldsm4(b[nxt][jj], base + offB[jj] + ckB);
            }
#pragma unroll
            for (int ii = 0; ii < 4; ii++)
#pragma unroll
                for (int jj = 0; jj < 4; jj++) {
                    mma16816(acc[ii][2 * jj],     a[cur][ii], &b[cur][jj][0]);
                    mma16816(acc[ii][2 * jj + 1], a[cur][ii], &b[cur][jj][2]);
                }
        }
        if (lane == 0) mbar_arrive(EMPTY(s));

        if ((i & (KT - 1)) == KT - 1) {
            int t = bid + (i >> 6) * NCTA;
            int m0, n0; tile_coords(t, m0, n0);
            const int mrow = m0 + wm * 64 + (lane >> 2);
            const int ncol = n0 + wn * 64 + (lane & 3) * 2;
#pragma unroll
            for (int ii = 0; ii < 4; ii++) {
#pragma unroll
                for (int jn = 0; jn < 8; jn++) {
                    float2 v0 = make_float2(acc[ii][jn][0], acc[ii][jn][1]);
                    float2 v1 = make_float2(acc[ii][jn][2], acc[ii][jn][3]);
                    *reinterpret_cast<float2*>(out + (size_t)(mrow + ii * 16) * DOUT + ncol + jn * 8)     = v0;
                    *reinterpret_cast<float2*>(out + (size_t)(mrow + ii * 16 + 8) * DOUT + ncol + jn * 8) = v1;
#pragma unroll
                    for (int v = 0; v < 4; v++) acc[ii][jn][v] = 0.f;
                }
            }
        }
    }
#undef FULL
#undef EMPTY
}

// ---------------- host launch ----------------
typedef CUresult (*encode_fn_t)(CUtensorMap*, CUtensorMapDataType, cuuint32_t, void*,
                                const cuuint64_t*, const cuuint64_t*, const cuuint32_t*,
                                const cuuint32_t*, CUtensorMapInterleave, CUtensorMapSwizzle,
                                CUtensorMapL2promotion, CUtensorMapFloatOOBfill);

extern "C" void kernel_launch(void* const* d_in, const int* in_sizes, int n_in,
                              void* d_out, int out_size) {
    const float* x = (const float*)d_in[0];
    const int*   W = (const int*)d_in[1];
    float* out = (float*)d_out;

    void* pa = nullptr; void* pb = nullptr;
    cudaGetSymbolAddress(&pa, g_A);
    cudaGetSymbolAddress(&pb, g_B);

    static encode_fn_t enc = nullptr;
    if (!enc) {
        cudaDriverEntryPointQueryResult st;
        cudaGetDriverEntryPointByVersion("cuTensorMapEncodeTiled", (void**)&enc,
                                         12000, cudaEnableDefault, &st);
    }
    CUtensorMap mA{}, mB{};
    {
        cuuint64_t dims[3] = {DIN, TOKENS, 1};
        cuuint64_t str[2]  = {DIN * 2ull, (cuuint64_t)TOKENS * DIN * 2ull};
        cuuint32_t box[3]  = {64, 128, 1};
        cuuint32_t es[3]   = {1, 1, 1};
        enc(&mA, CU_TENSOR_MAP_DATA_TYPE_FLOAT16, 3, pa, dims, str, box, es,
            CU_TENSOR_MAP_INTERLEAVE_NONE, CU_TENSOR_MAP_SWIZZLE_128B,
            CU_TENSOR_MAP_L2_PROMOTION_L2_128B, CU_TENSOR_MAP_FLOAT_OOB_FILL_NONE);
    }
    {
        cuuint64_t dims[3] = {DIN, DOUT, 1};
        cuuint64_t str[2]  = {DIN * 2ull, (cuuint64_t)DOUT * DIN * 2ull};
        cuuint32_t box[3]  = {64, 256, 1};
        cuuint32_t es[3]   = {1, 1, 1};
        enc(&mB, CU_TENSOR_MAP_DATA_TYPE_FLOAT16, 3, pb, dims, str, box, es,
            CU_TENSOR_MAP_INTERLEAVE_NONE, CU_TENSOR_MAP_SWIZZLE_128B,
            CU_TENSOR_MAP_L2_PROMOTION_L2_128B, CU_TENSOR_MAP_FLOAT_OOB_FILL_NONE);
    }

    conv_all<<<XB + WB, 256>>>((const float4*)x, W);

    cudaFuncSetAttribute(gemm_persist, cudaFuncAttributeMaxDynamicSharedMemorySize, SMEM_BYTES);
    gemm_persist<<<NCTA, 256, SMEM_BYTES>>>(mA, mB, out);
}